// round 2
// baseline (speedup 1.0000x reference)
#include <cuda_runtime.h>
#include <math.h>

// ---------------- problem constants ----------------
// x: (8192,1,28,28) -> conv0 3x3 SAME -> (B,32,28,28)
// -> conv1 2x2 s2 VALID -> (B,64,14,14)
// -> conv2 2x2 s2 VALID -> (B,128,7,7)
// -> pool+fc -> (B,10)
#define NB 8192

// ---------------- device scratch ----------------
__device__ float  g_y1[(size_t)NB * 64 * 14 * 14];   // conv1 pre-BN output (411MB)
__device__ float  g_y2[(size_t)NB * 128 * 7 * 7];    // conv2 pre-BN output (205MB)
// stats accumulators: [0:32) sum0 [32:64) sq0 [64:128) sum1 [128:192) sq1
//                     [192:320) sum2 [320:448) sq2
__device__ double g_acc[448];
// scale/shift: [0:32) stage0, [32:96) stage1, [96:224) stage2
__device__ float  g_scale[224];
__device__ float  g_shift[224];

// ---------------- zero stats ----------------
__global__ void k_zero() {
    int i = blockIdx.x * blockDim.x + threadIdx.x;
    if (i < 448) g_acc[i] = 0.0;
}

// ---------------- stage0 stats: conv0 (+bias), accumulate sum/sumsq ----------------
__global__ void __launch_bounds__(256) k_stats0(const float* __restrict__ x,
                                                const float* __restrict__ w0,
                                                const float* __restrict__ b0) {
    __shared__ float sx[30 * 28];   // rows 0 and 29 are zero padding (x rows -1, 28)
    __shared__ float sw[288];
    __shared__ float sb[32];
    __shared__ float ssum[32], ssq[32];
    int tid = threadIdx.x;
    int n = blockIdx.x;
    const float* xim = x + (size_t)n * 784;
    for (int i = tid; i < 840; i += 256) {
        int r = i / 28;
        sx[i] = (r >= 1 && r <= 28) ? xim[i - 28] : 0.f;
    }
    for (int i = tid; i < 288; i += 256) sw[i] = w0[i];   // FIX: was `if (tid<288)` with 256 threads
    if (tid < 32) { sb[tid] = b0[tid]; ssum[tid] = 0.f; ssq[tid] = 0.f; }
    __syncthreads();

#define LDROW(SR, X0, X1, X2) { const float* _p = &sx[(SR) * 28 + col]; \
        X0 = mL ? _p[-1] : 0.f; X1 = _p[0]; X2 = mR ? _p[1] : 0.f; }

    for (int task = tid; task < 896; task += 256) {
        int c = task / 28, col = task % 28;
        float w[9];
#pragma unroll
        for (int i = 0; i < 9; i++) w[i] = sw[c * 9 + i];
        float bias = sb[c];
        bool mL = col > 0, mR = col < 27;
        float a0, a1, a2, d0, d1, d2, e0, e1, e2;
        LDROW(0, a0, a1, a2);
        LDROW(1, d0, d1, d2);
        float ls = 0.f, lq = 0.f;
        for (int r = 0; r < 28; r++) {
            LDROW(r + 2, e0, e1, e2);
            float acc = bias;
            acc += w[0] * a0 + w[1] * a1 + w[2] * a2;
            acc += w[3] * d0 + w[4] * d1 + w[5] * d2;
            acc += w[6] * e0 + w[7] * e1 + w[8] * e2;
            ls += acc; lq += acc * acc;
            a0 = d0; a1 = d1; a2 = d2;
            d0 = e0; d1 = e1; d2 = e2;
        }
        atomicAdd(&ssum[c], ls);
        atomicAdd(&ssq[c], lq);
    }
    __syncthreads();
    if (tid < 32) {
        atomicAdd(&g_acc[tid], (double)ssum[tid]);
        atomicAdd(&g_acc[32 + tid], (double)ssq[tid]);
    }
}

// ---------------- finalize BN: scale/shift from accumulated stats ----------------
__global__ void k_fin(int acc_off, int C, double inv_n,
                      const float* __restrict__ g, const float* __restrict__ be, int so) {
    int c = threadIdx.x;
    if (c < C) {
        double mean = g_acc[acc_off + c] * inv_n;
        double var = g_acc[acc_off + C + c] * inv_n - mean * mean;
        float s = g[c] * rsqrtf((float)var + 1e-5f);
        g_scale[so + c] = s;
        g_shift[so + c] = be[c] - (float)mean * s;
    }
}

// ---------------- fused conv0+bn0+relu -> conv1(+bias), store y1, stats1 -------
// one block = half an image (a0 rows [half*14, half*14+14), conv1 out rows half*7..+7)
// smem floats: sa 12544 | sw1t 128*68=8704 | sx 448 | sw0 288 | sb0 32 | ssum 64 | ssq 64
__global__ void __launch_bounds__(128) k_conv1(const float* __restrict__ x,
                                               const float* __restrict__ w0,
                                               const float* __restrict__ b0,
                                               const float* __restrict__ w1,
                                               const float* __restrict__ b1) {
    extern __shared__ float sm[];
    float* sa   = sm;            // [32][14][28]
    float* sw1t = sm + 12544;    // [128][68] padded
    float* sx   = sm + 21248;    // [16][28]
    float* sw0  = sm + 21696;    // 288
    float* sb0  = sm + 21984;    // 32
    float* ssum = sm + 22016;    // 64
    float* ssq  = sm + 22080;    // 64   (total 22144 floats = 88576 B)

    int tid = threadIdx.x;
    int n = blockIdx.x >> 1;
    int half = blockIdx.x & 1;
    int r0 = half * 14;
    const float* xim = x + (size_t)n * 784;

    for (int i = tid; i < 448; i += 128) {
        int lr = i / 28;
        int gr = r0 - 1 + lr;
        sx[i] = (gr >= 0 && gr < 28) ? xim[gr * 28 + (i % 28)] : 0.f;
    }
    for (int i = tid; i < 288; i += 128) sw0[i] = w0[i];
    if (tid < 32) sb0[tid] = b0[tid];
    if (tid < 64) { ssum[tid] = 0.f; ssq[tid] = 0.f; }
    for (int i = tid; i < 8192; i += 128) {
        int co = i >> 7, kl = i & 127;
        sw1t[kl * 68 + co] = w1[i];
    }
    __syncthreads();

#define LDX(SR, X0, X1, X2) { const float* _p = &sx[(SR) * 28 + col]; \
        X0 = mL ? _p[-1] : 0.f; X1 = _p[0]; X2 = mR ? _p[1] : 0.f; }

    // conv0 + bn0 + relu into sa (14 rows of a0)
    for (int task = tid; task < 896; task += 128) {
        int c = task / 28, col = task % 28;
        float w[9];
#pragma unroll
        for (int i = 0; i < 9; i++) w[i] = sw0[c * 9 + i];
        float bias = sb0[c];
        float sc = g_scale[c], sh = g_shift[c];
        bool mL = col > 0, mR = col < 27;
        float a0, a1, a2, d0, d1, d2, e0, e1, e2;
        LDX(0, a0, a1, a2);
        LDX(1, d0, d1, d2);
#pragma unroll 2
        for (int lr = 0; lr < 14; lr++) {
            LDX(lr + 2, e0, e1, e2);
            float acc = bias;
            acc += w[0] * a0 + w[1] * a1 + w[2] * a2;
            acc += w[3] * d0 + w[4] * d1 + w[5] * d2;
            acc += w[6] * e0 + w[7] * e1 + w[8] * e2;
            float v = fmaf(acc, sc, sh);
            sa[c * 392 + lr * 28 + col] = fmaxf(v, 0.f);
            a0 = d0; a1 = d1; a2 = d2;
            d0 = e0; d1 = e1; d2 = e2;
        }
    }
    __syncthreads();

    // GEMM: C[64 co][98 p], thread tile 8co x 7p, 112 active threads
    if (tid < 112) {
        int tco = tid / 14;           // 0..7
        int tp = tid % 14;            // 7 rows x 2 col-halves
        int oh = tp >> 1;
        int ow0 = (tp & 1) * 7;
        int co0 = tco * 8;
        float acc[8][7];
#pragma unroll
        for (int j = 0; j < 8; j++) {
            float bb = b1[co0 + j];
#pragma unroll
            for (int i = 0; i < 7; i++) acc[j][i] = bb;
        }
#pragma unroll 4
        for (int k = 0; k < 128; k++) {
            int ci = k >> 2, dy = (k >> 1) & 1, dx = k & 1;
            const float* ap = &sa[ci * 392 + (2 * oh + dy) * 28 + 2 * ow0 + dx];
            float av[7];
#pragma unroll
            for (int i = 0; i < 7; i++) av[i] = ap[2 * i];
            float4 w03 = *(const float4*)&sw1t[k * 68 + co0];
            float4 w47 = *(const float4*)&sw1t[k * 68 + co0 + 4];
            float wv[8] = { w03.x, w03.y, w03.z, w03.w, w47.x, w47.y, w47.z, w47.w };
#pragma unroll
            for (int j = 0; j < 8; j++)
#pragma unroll
                for (int i = 0; i < 7; i++)
                    acc[j][i] = fmaf(wv[j], av[i], acc[j][i]);
        }
        int oh_g = half * 7 + oh;
#pragma unroll
        for (int j = 0; j < 8; j++) {
            int co = co0 + j;
            float ls = 0.f, lq = 0.f;
            size_t base = ((size_t)(n * 64 + co) * 14 + oh_g) * 14 + ow0;
#pragma unroll
            for (int i = 0; i < 7; i++) {
                float v = acc[j][i];
                g_y1[base + i] = v;
                ls += v; lq += v * v;
            }
            atomicAdd(&ssum[co], ls);
            atomicAdd(&ssq[co], lq);
        }
    }
    __syncthreads();
    if (tid < 64) {
        atomicAdd(&g_acc[64 + tid], (double)ssum[tid]);
        atomicAdd(&g_acc[128 + tid], (double)ssq[tid]);
    }
}

// ---------------- fused bn1+relu -> conv2(+bias), store y2, stats2 -------------
// one block = 2 images. smem: sa 2*64*196=25088 | swc 128*132=16896 | ssum/ssq 256
__global__ void __launch_bounds__(224) k_conv2(const float* __restrict__ w2,
                                               const float* __restrict__ b2) {
    extern __shared__ float sm[];
    float* sa   = sm;           // [2][64][196]
    float* swc  = sm + 25088;   // [128][132] padded (one K-chunk of W2^T)
    float* ssum = sm + 41984;   // 128
    float* ssq  = sm + 42112;   // 128  (total 42240 floats = 168960 B)
    int tid = threadIdx.x;
    int n0 = blockIdx.x * 2;
    if (tid < 128) { ssum[tid] = 0.f; ssq[tid] = 0.f; }

    // load y1 (2 images) with bn1+relu applied
    const float4* y1v = (const float4*)(g_y1 + (size_t)n0 * 12544);
    float4* sav = (float4*)sa;
    for (int i = tid; i < 6272; i += 224) {
        int ci = (i / 49) & 63;
        float sc = g_scale[32 + ci], sh = g_shift[32 + ci];
        float4 v = y1v[i];
        v.x = fmaxf(fmaf(v.x, sc, sh), 0.f);
        v.y = fmaxf(fmaf(v.y, sc, sh), 0.f);
        v.z = fmaxf(fmaf(v.z, sc, sh), 0.f);
        v.w = fmaxf(fmaf(v.w, sc, sh), 0.f);
        sav[i] = v;
    }

    // GEMM per image: C[128 co][49 p], thread tile 8co x 7ow, 2x112 threads
    int img = tid / 112, tt = tid % 112;
    int tco = tt / 7;            // 0..15
    int oh = tt % 7;
    int co0 = tco * 8;
    float acc[8][7];
#pragma unroll
    for (int j = 0; j < 8; j++) {
        float bb = b2[co0 + j];
#pragma unroll
        for (int i = 0; i < 7; i++) acc[j][i] = bb;
    }
    const float* saimg = sa + img * 12544;

    for (int kc = 0; kc < 2; kc++) {
        __syncthreads();
        for (int idx = tid; idx < 16384; idx += 224) {
            int co = idx >> 7, kl = idx & 127;
            swc[kl * 132 + co] = w2[co * 256 + kc * 128 + kl];
        }
        __syncthreads();
#pragma unroll 4
        for (int kl = 0; kl < 128; kl++) {
            int k = kc * 128 + kl;
            int ci = k >> 2, dy = (k >> 1) & 1, dx = k & 1;
            const float* ap = saimg + ci * 196 + (2 * oh + dy) * 14 + dx;
            float av[7];
#pragma unroll
            for (int i = 0; i < 7; i++) av[i] = ap[2 * i];
            float4 w03 = *(const float4*)&swc[kl * 132 + co0];
            float4 w47 = *(const float4*)&swc[kl * 132 + co0 + 4];
            float wv[8] = { w03.x, w03.y, w03.z, w03.w, w47.x, w47.y, w47.z, w47.w };
#pragma unroll
            for (int j = 0; j < 8; j++)
#pragma unroll
                for (int i = 0; i < 7; i++)
                    acc[j][i] = fmaf(wv[j], av[i], acc[j][i]);
        }
    }

    int n = n0 + img;
#pragma unroll
    for (int j = 0; j < 8; j++) {
        int co = co0 + j;
        float ls = 0.f, lq = 0.f;
        size_t base = (size_t)(n * 128 + co) * 49 + oh * 7;
#pragma unroll
        for (int i = 0; i < 7; i++) {
            float v = acc[j][i];
            g_y2[base + i] = v;
            ls += v; lq += v * v;
        }
        atomicAdd(&ssum[co], ls);
        atomicAdd(&ssq[co], lq);
    }
    __syncthreads();
    if (tid < 128) {
        atomicAdd(&g_acc[192 + tid], (double)ssum[tid]);
        atomicAdd(&g_acc[320 + tid], (double)ssq[tid]);
    }
}

// ---------------- bn2+relu + global avg pool + FC ----------------
__global__ void __launch_bounds__(128) k_head(const float* __restrict__ wfc,
                                              const float* __restrict__ bfc,
                                              float* __restrict__ out) {
    __shared__ float sraw[6272];
    __shared__ float pooled[128];
    int tid = threadIdx.x, n = blockIdx.x;
    const float* y2 = g_y2 + (size_t)n * 6272;
    for (int i = tid; i < 6272; i += 128) sraw[i] = y2[i];
    __syncthreads();
    {
        int c = tid;
        float sc = g_scale[96 + c], sh = g_shift[96 + c];
        float s = 0.f;
        const float* p = &sraw[c * 49];
#pragma unroll
        for (int i = 0; i < 49; i++) s += fmaxf(fmaf(p[i], sc, sh), 0.f);
        pooled[c] = s * (1.f / 49.f);
    }
    __syncthreads();
    if (tid < 10) {
        float o = bfc[tid];
        const float* wr = wfc + tid * 128;
#pragma unroll 8
        for (int c = 0; c < 128; c++) o = fmaf(pooled[c], wr[c], o);
        out[(size_t)n * 10 + tid] = o;
    }
}

// ---------------- launch ----------------
extern "C" void kernel_launch(void* const* d_in, const int* in_sizes, int n_in,
                              void* d_out, int out_size) {
    const float* x   = (const float*)d_in[0];
    const float* w0  = (const float*)d_in[1];
    const float* b0  = (const float*)d_in[2];
    const float* g0  = (const float*)d_in[3];
    const float* be0 = (const float*)d_in[4];
    const float* w1  = (const float*)d_in[5];
    const float* b1  = (const float*)d_in[6];
    const float* g1  = (const float*)d_in[7];
    const float* be1 = (const float*)d_in[8];
    const float* w2  = (const float*)d_in[9];
    const float* b2  = (const float*)d_in[10];
    const float* g2  = (const float*)d_in[11];
    const float* be2 = (const float*)d_in[12];
    const float* wfc = (const float*)d_in[13];
    const float* bfc = (const float*)d_in[14];
    float* out = (float*)d_out;

    cudaFuncSetAttribute(k_conv1, cudaFuncAttributeMaxDynamicSharedMemorySize, 88576);
    cudaFuncSetAttribute(k_conv2, cudaFuncAttributeMaxDynamicSharedMemorySize, 168960);

    k_zero<<<2, 256>>>();
    k_stats0<<<NB, 256>>>(x, w0, b0);
    k_fin<<<1, 128>>>(0, 32, 1.0 / (8192.0 * 784.0), g0, be0, 0);
    k_conv1<<<NB * 2, 128, 88576>>>(x, w0, b0, w1, b1);
    k_fin<<<1, 128>>>(64, 64, 1.0 / (8192.0 * 196.0), g1, be1, 32);
    k_conv2<<<NB / 2, 224, 168960>>>(w2, b2);
    k_fin<<<1, 128>>>(192, 128, 1.0 / (8192.0 * 49.0), g2, be2, 96);
    k_head<<<NB, 128>>>(wfc, bfc, out);
}